// round 14
// baseline (speedup 1.0000x reference)
#include <cuda_runtime.h>
#include <cuda_bf16.h>

#define DEPTH        4096
#define NTHREADS     512     /* one thread per 8 samples per row */
#define ROWS_PER_CTA 8
#define HKC          0.70710678118654752440f

// Rotated-pipeline wavelet layer (R7 skeleton, software-pipelined phases).
// Per iteration r:  [gather LDS row r]  ||  [dec+STS row r+1]  ||  [rec+STG row r]
// The gathers are issued first so their latency (random LDS, ~4x conflicts)
// is hidden behind the next row's butterfly + STS; one barrier per row.
//
// Reference slice map (reproduced exactly, incl. overlapping slices):
//   coeff_lst = [ g[0:256], g[2048:2304], g[1024:1536], g[512:1536], g[256:2304] ]
__global__ __launch_bounds__(NTHREADS, 2)
void wavelet_fused_kernel(const float* __restrict__ x,
                          const float* __restrict__ vec_b,
                          const float* __restrict__ vec_g,
                          const float* __restrict__ vec_s,
                          const int*  __restrict__ perm,
                          float* __restrict__ out)
{
    __shared__ float c[2][DEPTH];                 // 32 KB double buffer

    const int t  = threadIdx.x;
    const int th = t >> 1;                        // thread-pair index

    // ---- persistent: perm indices + gather weights -----------------------
    const int  p0 = __ldg(&perm[th]);
    const int  p1 = __ldg(&perm[2048 + th]);
    const int  p2 = __ldg(&perm[1024 + t]);
    const int2 p3 = __ldg(reinterpret_cast<const int2*>(&perm[512 + 2 * t]));
    const int4 p4 = __ldg(reinterpret_cast<const int4*>(&perm[256 + 4 * t]));

    const float  w0 = __ldg(&vec_g[th]);
    const float  w1 = __ldg(&vec_g[2048 + th]);
    const float  w2 = __ldg(&vec_g[1024 + t]);
    const float2 w3 = __ldg(reinterpret_cast<const float2*>(&vec_g[512 + 2 * t]));
    const float4 w4 = __ldg(reinterpret_cast<const float4*>(&vec_g[256 + 4 * t]));

    const float H2 = HKC * HKC;
    const float H3 = H2 * HKC;
    const float H4 = H2 * H2;

    const size_t base = (size_t)blockIdx.x * ROWS_PER_CTA * DEPTH;
    const float4* x4  = reinterpret_cast<const float4*>(x + base);
    float4*       o4  = reinterpret_cast<float4*>(out + base);
    const float4* bp4 = reinterpret_cast<const float4*>(vec_b) + 2 * t;
    const float4* sp4 = reinterpret_cast<const float4*>(vec_s) + 2 * t;

    // ---- prologue: dec row 0 into c[0], preload row 1 --------------------
    {
        const float4 xv0 = __ldcs(&x4[2 * t]);
        const float4 xv1 = __ldcs(&x4[2 * t + 1]);
        const float4 bv0 = __ldg(&bp4[0]);
        const float4 bv1 = __ldg(&bp4[1]);
        const float y0 = xv0.x * bv0.x, y1 = xv0.y * bv0.y;
        const float y2 = xv0.z * bv0.z, y3 = xv0.w * bv0.w;
        const float y4 = xv1.x * bv1.x, y5 = xv1.y * bv1.y;
        const float y6 = xv1.z * bv1.z, y7 = xv1.w * bv1.w;

        float* cb = c[0];
        float4 d1;
        d1.x = (y0 - y1) * HKC;  d1.y = (y2 - y3) * HKC;
        d1.z = (y4 - y5) * HKC;  d1.w = (y6 - y7) * HKC;
        *reinterpret_cast<float4*>(&cb[2048 + 4 * t]) = d1;
        const float s1a = y0 + y1, s1b = y2 + y3, s1c = y4 + y5, s1d = y6 + y7;
        float2 d2;
        d2.x = (s1a - s1b) * H2;  d2.y = (s1c - s1d) * H2;
        *reinterpret_cast<float2*>(&cb[1024 + 2 * t]) = d2;
        const float s2a = s1a + s1b, s2b = s1c + s1d;
        cb[512 + t] = (s2a - s2b) * H3;
        const float s3  = s2a + s2b;
        const float s3o = __shfl_xor_sync(0xffffffffu, s3, 1);
        if (t & 1) cb[256 + th] = (s3o - s3) * H4;
        else       cb[th]       = (s3 + s3o) * H4;
    }
    float4 xv0 = __ldcs(&x4[1024 + 2 * t]);       // row 1 in flight
    float4 xv1 = __ldcs(&x4[1024 + 2 * t + 1]);
    __syncthreads();

    #pragma unroll 1
    for (int r = 0; r < ROWS_PER_CTA; ++r) {
        const float* cb = c[r & 1];
        float*       cn = c[(r + 1) & 1];

        // ---- (1) gather row r: issue LDS first, consume last -------------
        const float G0  = w0  * cb[p0];
        const float G1  = w1  * cb[p1];
        const float G2  = w2  * cb[p2];
        const float G3x = w3.x * cb[p3.x];
        const float G3y = w3.y * cb[p3.y];
        const float G4x = w4.x * cb[p4.x];
        const float G4y = w4.y * cb[p4.y];
        const float G4z = w4.z * cb[p4.z];
        const float G4w = w4.w * cb[p4.w];

        // ---- (2) dec row r+1 into cn (independent of the gathers) --------
        if (r + 1 < ROWS_PER_CTA) {
            const float4 bv0 = __ldg(&bp4[0]);
            const float4 bv1 = __ldg(&bp4[1]);
            const float y0 = xv0.x * bv0.x, y1 = xv0.y * bv0.y;
            const float y2 = xv0.z * bv0.z, y3 = xv0.w * bv0.w;
            const float y4 = xv1.x * bv1.x, y5 = xv1.y * bv1.y;
            const float y6 = xv1.z * bv1.z, y7 = xv1.w * bv1.w;

            // prefetch row r+2 into the freed x registers
            if (r + 2 < ROWS_PER_CTA) {
                const float4* xn = x4 + (size_t)(r + 2) * (DEPTH / 4);
                xv0 = __ldcs(&xn[2 * t]);
                xv1 = __ldcs(&xn[2 * t + 1]);
            }

            float4 d1;
            d1.x = (y0 - y1) * HKC;  d1.y = (y2 - y3) * HKC;
            d1.z = (y4 - y5) * HKC;  d1.w = (y6 - y7) * HKC;
            *reinterpret_cast<float4*>(&cn[2048 + 4 * t]) = d1;
            const float s1a = y0 + y1, s1b = y2 + y3, s1c = y4 + y5, s1d = y6 + y7;
            float2 d2;
            d2.x = (s1a - s1b) * H2;  d2.y = (s1c - s1d) * H2;
            *reinterpret_cast<float2*>(&cn[1024 + 2 * t]) = d2;
            const float s2a = s1a + s1b, s2b = s1c + s1d;
            cn[512 + t] = (s2a - s2b) * H3;
            const float s3  = s2a + s2b;
            const float s3o = __shfl_xor_sync(0xffffffffu, s3, 1);
            if (t & 1) cn[256 + th] = (s3o - s3) * H4;
            else       cn[th]       = (s3 + s3o) * H4;
        }

        // ---- (3) rec row r from the gathered values, store ---------------
        const float4 sv0 = __ldg(&sp4[0]);
        const float4 sv1 = __ldg(&sp4[1]);

        const float r1  = ((t & 1) ? (G0 - G1) : (G0 + G1)) * HKC;
        const float r2a = (r1 + G2) * HKC;
        const float r2b = (r1 - G2) * HKC;
        const float r3a = (r2a + G3x) * HKC;
        const float r3b = (r2a - G3x) * HKC;
        const float r3c = (r2b + G3y) * HKC;
        const float r3d = (r2b - G3y) * HKC;

        float4 o0, o1;
        o0.x = (r3a + G4x) * HKC * sv0.x;  o0.y = (r3a - G4x) * HKC * sv0.y;
        o0.z = (r3b + G4y) * HKC * sv0.z;  o0.w = (r3b - G4y) * HKC * sv0.w;
        o1.x = (r3c + G4z) * HKC * sv1.x;  o1.y = (r3c - G4z) * HKC * sv1.y;
        o1.z = (r3d + G4w) * HKC * sv1.z;  o1.w = (r3d - G4w) * HKC * sv1.w;

        float4* orow = o4 + (size_t)r * (DEPTH / 4);
        __stcs(&orow[2 * t],     o0);
        __stcs(&orow[2 * t + 1], o1);

        // one barrier per row: publishes cn for iter r+1, and guarantees all
        // gathers from cb completed before iter r+2 overwrites it
        __syncthreads();
    }
}

extern "C" void kernel_launch(void* const* d_in, const int* in_sizes, int n_in,
                              void* d_out, int out_size)
{
    const float* x     = (const float*)d_in[0];
    const float* vec_b = (const float*)d_in[1];
    const float* vec_g = (const float*)d_in[2];
    const float* vec_s = (const float*)d_in[3];
    const int*   perm  = (const int*)  d_in[4];
    float* out = (float*)d_out;

    const int batch = in_sizes[0] / DEPTH;            // 8192
    wavelet_fused_kernel<<<batch / ROWS_PER_CTA, NTHREADS>>>(x, vec_b, vec_g, vec_s, perm, out);
}